// round 14
// baseline (speedup 1.0000x reference)
#include <cuda_runtime.h>
#include <cuda_bf16.h>
#include <cstdint>

#define NN 100000
#define EE 1600000
#define FF 9
#define HH 128
#define NB64 ((NN + 63) / 64)          // 1563 row tiles (64 rows each)
#define NB_SCAN ((NN + 1023) / 1024)   // 98 scan blocks

// ---------------- scratch (static device memory; no allocations) ----------------
__device__ float g_zb[(size_t)NN * HH];                 // raw MLP output (pre-BN)
__device__ __nv_bfloat16 g_zahi[(size_t)NN * HH];       // gathered z, bf16 hi
__device__ __nv_bfloat16 g_zalo[(size_t)NN * HH];       // gathered z, bf16 lo
__device__ float g_z0[(size_t)NN * 12];                 // layer-0 aggregated features
__device__ int   g_rowptr[NN + 1];
__device__ int   g_cursor[NN];
__device__ int   g_col[EE];
__device__ int   g_bsums[128];
__device__ float g_partsum[NB64 * HH];
__device__ float g_partsq[NB64 * HH];
__device__ float g_bnscale[HH];
__device__ float g_bnshift[HH];
// pre-converted weights: [layer][n][k] bf16 hi/lo (w1 zero-padded in k for layer 0)
__device__ __nv_bfloat16 g_w1hi[5 * 128 * 128], g_w1lo[5 * 128 * 128];
__device__ __nv_bfloat16 g_w2hi[5 * 128 * 128], g_w2lo[5 * 128 * 128];

// ---------------- helpers ----------------
__device__ __forceinline__ uint32_t smem_u32(const void* p) {
    uint32_t a;
    asm("{ .reg .u64 t; cvta.to.shared.u64 t, %1; cvt.u32.u64 %0, t; }" : "=r"(a) : "l"(p));
    return a;
}
#define LDSM_X4(r0, r1, r2, r3, addr) \
    asm volatile("ldmatrix.sync.aligned.m8n8.x4.shared.b16 {%0,%1,%2,%3}, [%4];" \
                 : "=r"(r0), "=r"(r1), "=r"(r2), "=r"(r3) : "r"(addr))
#define MMA16816(d, a, b) \
    asm volatile("mma.sync.aligned.m16n8k16.row.col.f32.bf16.bf16.f32 " \
                 "{%0,%1,%2,%3},{%4,%5,%6,%7},{%8,%9},{%0,%1,%2,%3};" \
                 : "+f"((d)[0]), "+f"((d)[1]), "+f"((d)[2]), "+f"((d)[3]) \
                 : "r"((a)[0]), "r"((a)[1]), "r"((a)[2]), "r"((a)[3]), "r"((b)[0]), "r"((b)[1]))

__device__ __forceinline__ uint32_t pack_hi(float a, float b, float& ra, float& rb) {
    __nv_bfloat16 ha = __float2bfloat16_rn(a);
    __nv_bfloat16 hb = __float2bfloat16_rn(b);
    ra = a - __bfloat162float(ha);
    rb = b - __bfloat162float(hb);
    return (uint32_t)__bfloat16_as_ushort(ha) | ((uint32_t)__bfloat16_as_ushort(hb) << 16);
}
__device__ __forceinline__ uint32_t pack_lo(float ra, float rb) {
    return (uint32_t)__bfloat16_as_ushort(__float2bfloat16_rn(ra)) |
           ((uint32_t)__bfloat16_as_ushort(__float2bfloat16_rn(rb)) << 16);
}

// SMEM: biases | A hi/lo (64x136) | W hi/lo (128x136, reused W1 then W2)
#define TSTR 136
#define ATB (64 * TSTR * 2)    // 17408
#define WTB (128 * TSTR * 2)   // 34816
#define SM_B1   0
#define SM_B2   512
#define SM_AHI  1024
#define SM_ALO  (SM_AHI + ATB)
#define SM_WHI  (SM_ALO + ATB)
#define SM_WLO  (SM_WHI + WTB)
#define SM_TOTAL (SM_WLO + WTB)   // 105472 B -> 2 blocks/SM
#define SM_REDS SM_AHI
#define SM_REDQ (SM_AHI + 8192)

// bf16x3 emulated-fp32 GEMM over a 64x128 tile; 8 warps (2x4), per-warp 32x32; term-outer
template <int KS>
__device__ __forceinline__ void gemm3(uint32_t sAhi, uint32_t sAlo, uint32_t sWhi, uint32_t sWlo,
                                      int warp_m, int warp_n, int lane, float acc[2][4][4]) {
#pragma unroll
    for (int term = 0; term < 3; term++) {
        uint32_t Ab = (term == 2) ? sAlo : sAhi;
        uint32_t Bb = (term == 1) ? sWlo : sWhi;
#pragma unroll
        for (int ks = 0; ks < KS; ks++) {
            uint32_t a[2][4], b[4][2];
#pragma unroll
            for (int mt = 0; mt < 2; mt++) {
                uint32_t addr = Ab + (uint32_t)(((warp_m * 32 + mt * 16 + (lane & 15)) * TSTR
                                                 + ks * 16 + ((lane >> 4) << 3)) * 2);
                LDSM_X4(a[mt][0], a[mt][1], a[mt][2], a[mt][3], addr);
            }
#pragma unroll
            for (int nh = 0; nh < 2; nh++) {
                uint32_t addr = Bb + (uint32_t)(((warp_n * 32 + nh * 16 + ((lane >> 4) << 3) + (lane & 7)) * TSTR
                                                 + ks * 16 + (((lane >> 3) & 1) << 3)) * 2);
                LDSM_X4(b[nh * 2][0], b[nh * 2][1], b[nh * 2 + 1][0], b[nh * 2 + 1][1], addr);
            }
#pragma unroll
            for (int mt = 0; mt < 2; mt++)
#pragma unroll
                for (int nt = 0; nt < 4; nt++) MMA16816(acc[mt][nt], a[mt], b[nt]);
        }
    }
}

// ---------------- weight pre-conversion ----------------
__global__ void k_wconv(const float* __restrict__ w1_0, const float* __restrict__ w2_0,
                        const float* __restrict__ ws1, const float* __restrict__ ws2) {
    int i = blockIdx.x * 256 + threadIdx.x;
    if (i >= 5 * 16384 * 2) return;
    int kind = (i >= 5 * 16384);
    int j = i - kind * 5 * 16384;
    int l = j >> 14;
    int r = j & 16383;
    int n = r >> 7, k = r & 127;
    float v;
    if (kind == 0) {
        if (l == 0) v = (k < FF) ? w1_0[k * 128 + n] : 0.f;
        else        v = ws1[(size_t)(l - 1) * 16384 + k * 128 + n];
    } else {
        if (l == 0) v = w2_0[k * 128 + n];
        else        v = ws2[(size_t)(l - 1) * 16384 + k * 128 + n];
    }
    __nv_bfloat16 h = __float2bfloat16_rn(v);
    __nv_bfloat16 lo = __float2bfloat16_rn(v - __bfloat162float(h));
    if (kind == 0) { g_w1hi[j] = h; g_w1lo[j] = lo; }
    else           { g_w2hi[j] = h; g_w2lo[j] = lo; }
}

// ---------------- CSR build ----------------
__global__ void k_hist(const int* __restrict__ dst) {
    int e = blockIdx.x * blockDim.x + threadIdx.x;
    if (e < EE) atomicAdd(&g_cursor[dst[e]], 1);
}
__global__ void k_scan1() {
    __shared__ int sm[1024];
    int i = blockIdx.x * 1024 + threadIdx.x;
    int v = (i < NN) ? g_cursor[i] : 0;
    sm[threadIdx.x] = v;
    __syncthreads();
    for (int off = 1; off < 1024; off <<= 1) {
        int t = (threadIdx.x >= off) ? sm[threadIdx.x - off] : 0;
        __syncthreads();
        sm[threadIdx.x] += t;
        __syncthreads();
    }
    if (i < NN) g_rowptr[i] = sm[threadIdx.x] - v;
    if (threadIdx.x == 1023) g_bsums[blockIdx.x] = sm[1023];
}
__global__ void k_scan2() {
    __shared__ int sm[128];
    int t = threadIdx.x;
    int v = (t < NB_SCAN) ? g_bsums[t] : 0;
    sm[t] = v;
    __syncthreads();
    for (int off = 1; off < 128; off <<= 1) {
        int u = (t >= off) ? sm[t - off] : 0;
        __syncthreads();
        sm[t] += u;
        __syncthreads();
    }
    if (t < NB_SCAN) g_bsums[t] = sm[t] - v;
    if (t == 127) g_rowptr[NN] = sm[127];
}
__global__ void k_scan3() {
    int i = blockIdx.x * 1024 + threadIdx.x;
    if (i < NN) {
        int v = g_rowptr[i] + g_bsums[blockIdx.x];
        g_rowptr[i] = v;
        g_cursor[i] = v;
    }
}
__global__ void k_fill(const int* __restrict__ src, const int* __restrict__ dst) {
    int e = blockIdx.x * blockDim.x + threadIdx.x;
    if (e < EE) {
        int d = dst[e];
        int p = atomicAdd(&g_cursor[d], 1);
        g_col[p] = src[e];
    }
}

// ---------------- aggregation (R6 shfl form) ----------------
__global__ void k_gather0(const float* __restrict__ x) {
    int w = (blockIdx.x * blockDim.x + threadIdx.x) >> 5;
    int lane = threadIdx.x & 31;
    if (w >= NN) return;
    float acc = (lane < FF) ? x[(size_t)w * FF + lane] : 0.f;
    int e0 = g_rowptr[w], e1 = g_rowptr[w + 1];
    for (int eb = e0; eb < e1; eb += 32) {
        int n = min(32, e1 - eb);
        int col = (eb + lane < e1) ? g_col[eb + lane] : 0;
        for (int j = 0; j < n; j++) {
            int s = __shfl_sync(0xffffffff, col, j);
            if (lane < FF) acc += x[(size_t)s * FF + lane];
        }
    }
    if (lane < 12) g_z0[(size_t)w * 12 + lane] = (lane < FF) ? acc : 0.f;
}
// fused: h = relu(zb*sc+sh) self + neighbors; z = sum -> bf16 hi/lo arrays (MLP-ready)
__global__ void k_gatherBN() {
    int w = (blockIdx.x * blockDim.x + threadIdx.x) >> 5;
    int lane = threadIdx.x & 31;
    if (w >= NN) return;
    float4 sc = *(const float4*)&g_bnscale[lane << 2];
    float4 sh = *(const float4*)&g_bnshift[lane << 2];
    const float4* hv = (const float4*)g_zb;
    float4 z = hv[(size_t)w * 32 + lane];
    float4 acc;
    acc.x = fmaxf(fmaf(z.x, sc.x, sh.x), 0.f);
    acc.y = fmaxf(fmaf(z.y, sc.y, sh.y), 0.f);
    acc.z = fmaxf(fmaf(z.z, sc.z, sh.z), 0.f);
    acc.w = fmaxf(fmaf(z.w, sc.w, sh.w), 0.f);
    int e0 = g_rowptr[w], e1 = g_rowptr[w + 1];
    for (int eb = e0; eb < e1; eb += 32) {
        int n = min(32, e1 - eb);
        int col = (eb + lane < e1) ? g_col[eb + lane] : 0;
        for (int j = 0; j < n; j++) {
            int s = __shfl_sync(0xffffffff, col, j);
            float4 v = hv[(size_t)s * 32 + lane];
            acc.x += fmaxf(fmaf(v.x, sc.x, sh.x), 0.f);
            acc.y += fmaxf(fmaf(v.y, sc.y, sh.y), 0.f);
            acc.z += fmaxf(fmaf(v.z, sc.z, sh.z), 0.f);
            acc.w += fmaxf(fmaf(v.w, sc.w, sh.w), 0.f);
        }
    }
    float r0, r1, r2, r3;
    uint32_t h01 = pack_hi(acc.x, acc.y, r0, r1);
    uint32_t h23 = pack_hi(acc.z, acc.w, r2, r3);
    ((uint2*)g_zahi)[(size_t)w * 32 + lane] = make_uint2(h01, h23);
    ((uint2*)g_zalo)[(size_t)w * 32 + lane] = make_uint2(pack_lo(r0, r1), pack_lo(r2, r3));
}

// ---------------- tensor-core fused MLP + BN partials ----------------
// 64-row tiles, 8 warps (2x4), 2 blocks/SM. W buffer staged twice (W1 then W2).
template <int K1>
__global__ void __launch_bounds__(256, 2) k_mlp_mma(
    int layer, const float* __restrict__ b1g, const float* __restrict__ b2g)
{
    extern __shared__ char smem[];
    uint32_t sb = smem_u32(smem);
    float* b1s = (float*)(smem + SM_B1);
    float* b2s = (float*)(smem + SM_B2);
    const int t = threadIdx.x, lane = t & 31, wid = t >> 5;
    const int warp_m = wid & 1, warp_n = wid >> 1;
    const int row0 = blockIdx.x * 64;

    if (t < 128) { b1s[t] = b1g[t]; b2s[t] = b2g[t]; }

    // ---- stage A tile (64 rows) ----
    if (K1 == 128) {
        const uint4 zero4 = make_uint4(0u, 0u, 0u, 0u);
        for (int i = t; i < 64 * 16; i += 256) {
            int r = i >> 4, kk = (i & 15) << 3;
            int gr = row0 + r;
            uint4 vh = zero4, vl = zero4;
            if (gr < NN) {
                vh = *(const uint4*)(g_zahi + (size_t)gr * 128 + kk);
                vl = *(const uint4*)(g_zalo + (size_t)gr * 128 + kk);
            }
            *(uint4*)(smem + SM_AHI + (r * TSTR + kk) * 2) = vh;
            *(uint4*)(smem + SM_ALO + (r * TSTR + kk) * 2) = vl;
        }
    } else {
        for (int i = t; i < 64 * 8; i += 256) {
            int r = i >> 3, c = (i & 7) << 1, gr = row0 + r;
            float a = 0.f, b = 0.f;
            if (gr < NN && c < 9) a = g_z0[(size_t)gr * 12 + c];
            if (gr < NN && c + 1 < 9) b = g_z0[(size_t)gr * 12 + c + 1];
            float ra, rb;
            *(uint32_t*)(smem + SM_AHI + (r * TSTR + c) * 2) = pack_hi(a, b, ra, rb);
            *(uint32_t*)(smem + SM_ALO + (r * TSTR + c) * 2) = pack_lo(ra, rb);
        }
    }
    // ---- stage W1 ----
    {
        const __nv_bfloat16* w1h = g_w1hi + (size_t)layer * 16384;
        const __nv_bfloat16* w1l = g_w1lo + (size_t)layer * 16384;
        constexpr int KC = K1 / 8;
        for (int i = t; i < 128 * KC; i += 256) {
            int n = i / KC, kk = (i % KC) << 3;
            *(uint4*)(smem + SM_WHI + (n * TSTR + kk) * 2) = *(const uint4*)(w1h + n * 128 + kk);
            *(uint4*)(smem + SM_WLO + (n * TSTR + kk) * 2) = *(const uint4*)(w1l + n * 128 + kk);
        }
    }
    __syncthreads();

    // ---- GEMM1 ----
    float acc[2][4][4];
#pragma unroll
    for (int mt = 0; mt < 2; mt++)
#pragma unroll
        for (int nt = 0; nt < 4; nt++)
#pragma unroll
            for (int i = 0; i < 4; i++) acc[mt][nt][i] = 0.f;
    gemm3<K1 / 16>(sb + SM_AHI, sb + SM_ALO, sb + SM_WHI, sb + SM_WLO, warp_m, warp_n, lane, acc);
    __syncthreads();   // GEMM1 reads of A and W done

    // ---- epilogue1: Y = relu(D1 + b1) -> A hi/lo ; concurrently stage W2 ----
#pragma unroll
    for (int mt = 0; mt < 2; mt++) {
#pragma unroll
        for (int nt = 0; nt < 4; nt++) {
            int r1 = warp_m * 32 + mt * 16 + (lane >> 2);
            int r2 = r1 + 8;
            int c = warp_n * 32 + nt * 8 + ((lane & 3) << 1);
            float bb0 = b1s[c], bb1 = b1s[c + 1];
            float y00 = fmaxf(acc[mt][nt][0] + bb0, 0.f);
            float y01 = fmaxf(acc[mt][nt][1] + bb1, 0.f);
            float y10 = fmaxf(acc[mt][nt][2] + bb0, 0.f);
            float y11 = fmaxf(acc[mt][nt][3] + bb1, 0.f);
            float ra, rb;
            *(uint32_t*)(smem + SM_AHI + (r1 * TSTR + c) * 2) = pack_hi(y00, y01, ra, rb);
            *(uint32_t*)(smem + SM_ALO + (r1 * TSTR + c) * 2) = pack_lo(ra, rb);
            *(uint32_t*)(smem + SM_AHI + (r2 * TSTR + c) * 2) = pack_hi(y10, y11, ra, rb);
            *(uint32_t*)(smem + SM_ALO + (r2 * TSTR + c) * 2) = pack_lo(ra, rb);
        }
    }
    // stage W2 into the same W buffers
    {
        const __nv_bfloat16* w2h = g_w2hi + (size_t)layer * 16384;
        const __nv_bfloat16* w2l = g_w2lo + (size_t)layer * 16384;
        for (int i = t; i < 128 * 16; i += 256) {
            int n = i >> 4, kk = (i & 15) << 3;
            *(uint4*)(smem + SM_WHI + (n * TSTR + kk) * 2) = *(const uint4*)(w2h + n * 128 + kk);
            *(uint4*)(smem + SM_WLO + (n * TSTR + kk) * 2) = *(const uint4*)(w2l + n * 128 + kk);
        }
    }
    __syncthreads();

    // ---- GEMM2 ----
#pragma unroll
    for (int mt = 0; mt < 2; mt++)
#pragma unroll
        for (int nt = 0; nt < 4; nt++)
#pragma unroll
            for (int i = 0; i < 4; i++) acc[mt][nt][i] = 0.f;
    gemm3<8>(sb + SM_AHI, sb + SM_ALO, sb + SM_WHI, sb + SM_WLO, warp_m, warp_n, lane, acc);
    __syncthreads();

    // ---- epilogue2: y = D2 + b2 -> g_zb ; BN partials ----
    float s[8], q[8];
#pragma unroll
    for (int i = 0; i < 8; i++) { s[i] = 0.f; q[i] = 0.f; }
#pragma unroll
    for (int mt = 0; mt < 2; mt++) {
#pragma unroll
        for (int nt = 0; nt < 4; nt++) {
            int r1 = warp_m * 32 + mt * 16 + (lane >> 2);
            int r2 = r1 + 8;
            int c = warp_n * 32 + nt * 8 + ((lane & 3) << 1);
            int gr1 = row0 + r1, gr2 = row0 + r2;
            float bb0 = b2s[c], bb1 = b2s[c + 1];
            float y00 = acc[mt][nt][0] + bb0, y01 = acc[mt][nt][1] + bb1;
            float y10 = acc[mt][nt][2] + bb0, y11 = acc[mt][nt][3] + bb1;
            if (gr1 < NN) {
                *(float2*)(g_zb + (size_t)gr1 * 128 + c) = make_float2(y00, y01);
                s[nt * 2] += y00; q[nt * 2] += y00 * y00;
                s[nt * 2 + 1] += y01; q[nt * 2 + 1] += y01 * y01;
            }
            if (gr2 < NN) {
                *(float2*)(g_zb + (size_t)gr2 * 128 + c) = make_float2(y10, y11);
                s[nt * 2] += y10; q[nt * 2] += y10 * y10;
                s[nt * 2 + 1] += y11; q[nt * 2 + 1] += y11 * y11;
            }
        }
    }
    float* red_s = (float*)(smem + SM_REDS);
    float* red_q = (float*)(smem + SM_REDQ);
    int slot = warp_m * 8 + (lane >> 2);   // 16 slots
#pragma unroll
    for (int nt = 0; nt < 4; nt++) {
#pragma unroll
        for (int p = 0; p < 2; p++) {
            int col = warp_n * 32 + nt * 8 + ((lane & 3) << 1) + p;
            red_s[slot * 128 + col] = s[nt * 2 + p];
            red_q[slot * 128 + col] = q[nt * 2 + p];
        }
    }
    __syncthreads();
    if (t < 128) {
        float S = 0.f, Q = 0.f;
#pragma unroll
        for (int sl = 0; sl < 16; sl++) { S += red_s[sl * 128 + t]; Q += red_q[sl * 128 + t]; }
        g_partsum[blockIdx.x * 128 + t] = S;
        g_partsq[blockIdx.x * 128 + t] = Q;
    }
}

// ---------------- BN stats + final normalize ----------------
__global__ void k_bnstats(const float* __restrict__ gamma, const float* __restrict__ beta) {
    __shared__ float ssum[1024], ssq[1024];
    int c = threadIdx.x & 127;
    int p = threadIdx.x >> 7;
    float S = 0.f, Q = 0.f;
    for (int b = p; b < NB64; b += 8) {
        S += g_partsum[b * 128 + c];
        Q += g_partsq[b * 128 + c];
    }
    ssum[threadIdx.x] = S;
    ssq[threadIdx.x] = Q;
    __syncthreads();
    if (p == 0) {
        for (int r = 1; r < 8; r++) { S += ssum[r * 128 + c]; Q += ssq[r * 128 + c]; }
        float mean = S * (1.0f / NN);
        float var = Q * (1.0f / NN) - mean * mean;
        float e = var + 1e-5f;
        float inv = rsqrtf(e);
        inv = inv * (1.5f - 0.5f * e * inv * inv);
        float sc = inv * gamma[c];
        g_bnscale[c] = sc;
        g_bnshift[c] = beta[c] - mean * sc;
    }
}
__global__ void k_bnnorm(float* __restrict__ out) {
    int i = blockIdx.x * 256 + threadIdx.x;
    if (i >= NN * 32) return;
    int c4 = (i & 31) << 2;
    float4 v = ((const float4*)g_zb)[i];
    float4 sc = *(const float4*)&g_bnscale[c4];
    float4 sh = *(const float4*)&g_bnshift[c4];
    v.x = fmaxf(fmaf(v.x, sc.x, sh.x), 0.f);
    v.y = fmaxf(fmaf(v.y, sc.y, sh.y), 0.f);
    v.z = fmaxf(fmaf(v.z, sc.z, sh.z), 0.f);
    v.w = fmaxf(fmaf(v.w, sc.w, sh.w), 0.f);
    ((float4*)out)[i] = v;
}
__global__ void k_copybatch(const int* __restrict__ b, float* __restrict__ o) {
    int i = blockIdx.x * 256 + threadIdx.x;
    if (i < NN) o[i] = (float)b[i];
}

// ---------------- launch ----------------
extern "C" void kernel_launch(void* const* d_in, const int* in_sizes, int n_in,
                              void* d_out, int out_size) {
    const float* x       = (const float*)d_in[0];
    const int*   ei      = (const int*)d_in[1];
    const int*   batch   = (const int*)d_in[2];
    const float* w1_0    = (const float*)d_in[3];
    const float* b1_0    = (const float*)d_in[4];
    const float* w2_0    = (const float*)d_in[5];
    const float* b2_0    = (const float*)d_in[6];
    const float* gamma_0 = (const float*)d_in[7];
    const float* beta_0  = (const float*)d_in[8];
    const float* ws1     = (const float*)d_in[9];
    const float* bs1     = (const float*)d_in[10];
    const float* ws2     = (const float*)d_in[11];
    const float* bs2     = (const float*)d_in[12];
    const float* gammas  = (const float*)d_in[13];
    const float* betas   = (const float*)d_in[14];
    float* out = (float*)d_out;

    cudaFuncSetAttribute(k_mlp_mma<16>,  cudaFuncAttributeMaxDynamicSharedMemorySize, SM_TOTAL);
    cudaFuncSetAttribute(k_mlp_mma<128>, cudaFuncAttributeMaxDynamicSharedMemorySize, SM_TOTAL);

    void* curp = nullptr;
    cudaGetSymbolAddress(&curp, g_cursor);

    const int* src = ei;
    const int* dst = ei + EE;

    // ---- weight pre-conversion + CSR build ----
    k_wconv<<<(5 * 16384 * 2 + 255) / 256, 256>>>(w1_0, w2_0, ws1, ws2);
    cudaMemsetAsync(curp, 0, NN * sizeof(int), 0);
    k_hist<<<(EE + 511) / 512, 512>>>(dst);
    k_scan1<<<NB_SCAN, 1024>>>();
    k_scan2<<<1, 128>>>();
    k_scan3<<<NB_SCAN, 1024>>>();
    k_fill<<<(EE + 511) / 512, 512>>>(src, dst);

    const int GBLK = (NN * 32 + 255) / 256;

    // ---- layer 0 (F=9 -> H) ----
    k_gather0<<<GBLK, 256>>>(x);
    k_mlp_mma<16><<<NB64, 256, SM_TOTAL>>>(0, b1_0, b2_0);
    k_bnstats<<<1, 1024>>>(gamma_0, beta_0);

    // ---- layers 1..4 ----
    for (int l = 0; l < 4; l++) {
        const float* b1 = bs1 + (size_t)l * HH;
        const float* b2 = bs2 + (size_t)l * HH;
        const float* ga = gammas + (size_t)l * HH;
        const float* be = betas + (size_t)l * HH;
        k_gatherBN<<<GBLK, 256>>>();
        k_mlp_mma<128><<<NB64, 256, SM_TOTAL>>>(l + 1, b1, b2);
        k_bnstats<<<1, 1024>>>(ga, be);
    }
    // final normalize -> out
    k_bnnorm<<<(NN * 32 + 255) / 256, 256>>>(out);

    // ---- batch passthrough (float-converted) ----
    {
        float* bo = out + ((size_t)NN * HH);
        k_copybatch<<<(NN + 255) / 256, 256>>>(batch, bo);
    }
}

// round 15
// speedup vs baseline: 1.1836x; 1.1836x over previous
#include <cuda_runtime.h>
#include <cuda_bf16.h>
#include <cstdint>

#define NN 100000
#define EE 1600000
#define FF 9
#define HH 128
#define NBLK ((NN + 127) / 128)        // 782 row tiles
#define NB_SCAN ((NN + 1023) / 1024)   // 98 scan blocks

// ---------------- scratch (static device memory; no allocations) ----------------
__device__ float g_zb[(size_t)NN * HH];                 // raw MLP output (pre-BN)
__device__ __nv_bfloat16 g_zahi[(size_t)NN * HH];       // gathered z, bf16 hi
__device__ __nv_bfloat16 g_zalo[(size_t)NN * HH];       // gathered z, bf16 lo
__device__ float g_z0[(size_t)NN * 12];                 // layer-0 aggregated features
__device__ int   g_rowptr[NN + 1];
__device__ int   g_cursor[NN];
__device__ int   g_col[EE];
__device__ int   g_bsums[128];
__device__ float g_partsum[NBLK * HH];
__device__ float g_partsq[NBLK * HH];
__device__ float g_bnscale[HH];
__device__ float g_bnshift[HH];
// pre-converted weights: [layer][n][k] bf16 hi/lo (w1 zero-padded in k for layer 0)
__device__ __nv_bfloat16 g_w1hi[5 * 128 * 128], g_w1lo[5 * 128 * 128];
__device__ __nv_bfloat16 g_w2hi[5 * 128 * 128], g_w2lo[5 * 128 * 128];

// ---------------- helpers ----------------
__device__ __forceinline__ uint32_t smem_u32(const void* p) {
    uint32_t a;
    asm("{ .reg .u64 t; cvta.to.shared.u64 t, %1; cvt.u32.u64 %0, t; }" : "=r"(a) : "l"(p));
    return a;
}
#define LDSM_X4(r0, r1, r2, r3, addr) \
    asm volatile("ldmatrix.sync.aligned.m8n8.x4.shared.b16 {%0,%1,%2,%3}, [%4];" \
                 : "=r"(r0), "=r"(r1), "=r"(r2), "=r"(r3) : "r"(addr))
#define MMA16816(d, a, b) \
    asm volatile("mma.sync.aligned.m16n8k16.row.col.f32.bf16.bf16.f32 " \
                 "{%0,%1,%2,%3},{%4,%5,%6,%7},{%8,%9},{%0,%1,%2,%3};" \
                 : "+f"((d)[0]), "+f"((d)[1]), "+f"((d)[2]), "+f"((d)[3]) \
                 : "r"((a)[0]), "r"((a)[1]), "r"((a)[2]), "r"((a)[3]), "r"((b)[0]), "r"((b)[1]))

__device__ __forceinline__ uint32_t pack_hi(float a, float b, float& ra, float& rb) {
    __nv_bfloat16 ha = __float2bfloat16_rn(a);
    __nv_bfloat16 hb = __float2bfloat16_rn(b);
    ra = a - __bfloat162float(ha);
    rb = b - __bfloat162float(hb);
    return (uint32_t)__bfloat16_as_ushort(ha) | ((uint32_t)__bfloat16_as_ushort(hb) << 16);
}
__device__ __forceinline__ uint32_t pack_lo(float ra, float rb) {
    return (uint32_t)__bfloat16_as_ushort(__float2bfloat16_rn(ra)) |
           ((uint32_t)__bfloat16_as_ushort(__float2bfloat16_rn(rb)) << 16);
}

// SMEM offsets: biases | A hi/lo | W1 hi/lo | W2 hi/lo  ([128][136] bf16 tiles)
#define TSTR 136
#define TBYTES (128 * TSTR * 2)   // 34816
#define SM_B1   0
#define SM_B2   512
#define SM_AHI  1024
#define SM_ALO  (SM_AHI + TBYTES)
#define SM_W1HI (SM_ALO + TBYTES)
#define SM_W1LO (SM_W1HI + TBYTES)
#define SM_W2HI (SM_W1LO + TBYTES)
#define SM_W2LO (SM_W2HI + TBYTES)
#define SM_TOTAL (SM_W2LO + TBYTES)   // 209920 B
#define SM_REDS SM_AHI
#define SM_REDQ (SM_AHI + 8192)

// bf16x3 emulated-fp32 GEMM over a 128x128 tile (per-warp 64x32; 8 warps) — R13 term-outer form
template <int KS>
__device__ __forceinline__ void gemm3(uint32_t sAhi, uint32_t sAlo, uint32_t sWhi, uint32_t sWlo,
                                      int warp_m, int warp_n, int lane, float acc[4][4][4]) {
#pragma unroll
    for (int term = 0; term < 3; term++) {
        uint32_t Ab = (term == 2) ? sAlo : sAhi;
        uint32_t Bb = (term == 1) ? sWlo : sWhi;
#pragma unroll
        for (int ks = 0; ks < KS; ks++) {
            uint32_t a[4][4], b[4][2];
#pragma unroll
            for (int mt = 0; mt < 4; mt++) {
                uint32_t addr = Ab + (uint32_t)(((warp_m * 64 + mt * 16 + (lane & 15)) * TSTR
                                                 + ks * 16 + ((lane >> 4) << 3)) * 2);
                LDSM_X4(a[mt][0], a[mt][1], a[mt][2], a[mt][3], addr);
            }
#pragma unroll
            for (int nh = 0; nh < 2; nh++) {
                uint32_t addr = Bb + (uint32_t)(((warp_n * 32 + nh * 16 + ((lane >> 4) << 3) + (lane & 7)) * TSTR
                                                 + ks * 16 + (((lane >> 3) & 1) << 3)) * 2);
                LDSM_X4(b[nh * 2][0], b[nh * 2][1], b[nh * 2 + 1][0], b[nh * 2 + 1][1], addr);
            }
#pragma unroll
            for (int mt = 0; mt < 4; mt++)
#pragma unroll
                for (int nt = 0; nt < 4; nt++) MMA16816(acc[mt][nt], a[mt], b[nt]);
        }
    }
}

// ---------------- weight pre-conversion ----------------
__global__ void k_wconv(const float* __restrict__ w1_0, const float* __restrict__ w2_0,
                        const float* __restrict__ ws1, const float* __restrict__ ws2) {
    int i = blockIdx.x * 256 + threadIdx.x;
    if (i >= 5 * 16384 * 2) return;
    int kind = (i >= 5 * 16384);
    int j = i - kind * 5 * 16384;
    int l = j >> 14;
    int r = j & 16383;
    int n = r >> 7, k = r & 127;
    float v;
    if (kind == 0) {
        if (l == 0) v = (k < FF) ? w1_0[k * 128 + n] : 0.f;
        else        v = ws1[(size_t)(l - 1) * 16384 + k * 128 + n];
    } else {
        if (l == 0) v = w2_0[k * 128 + n];
        else        v = ws2[(size_t)(l - 1) * 16384 + k * 128 + n];
    }
    __nv_bfloat16 h = __float2bfloat16_rn(v);
    __nv_bfloat16 lo = __float2bfloat16_rn(v - __bfloat162float(h));
    if (kind == 0) { g_w1hi[j] = h; g_w1lo[j] = lo; }
    else           { g_w2hi[j] = h; g_w2lo[j] = lo; }
}

// ---------------- CSR build ----------------
__global__ void k_hist(const int* __restrict__ dst) {
    int e = blockIdx.x * blockDim.x + threadIdx.x;
    if (e < EE) atomicAdd(&g_cursor[dst[e]], 1);
}
__global__ void k_scan1() {
    __shared__ int sm[1024];
    int i = blockIdx.x * 1024 + threadIdx.x;
    int v = (i < NN) ? g_cursor[i] : 0;
    sm[threadIdx.x] = v;
    __syncthreads();
    for (int off = 1; off < 1024; off <<= 1) {
        int t = (threadIdx.x >= off) ? sm[threadIdx.x - off] : 0;
        __syncthreads();
        sm[threadIdx.x] += t;
        __syncthreads();
    }
    if (i < NN) g_rowptr[i] = sm[threadIdx.x] - v;
    if (threadIdx.x == 1023) g_bsums[blockIdx.x] = sm[1023];
}
__global__ void k_scan2() {
    __shared__ int sm[128];
    int t = threadIdx.x;
    int v = (t < NB_SCAN) ? g_bsums[t] : 0;
    sm[t] = v;
    __syncthreads();
    for (int off = 1; off < 128; off <<= 1) {
        int u = (t >= off) ? sm[t - off] : 0;
        __syncthreads();
        sm[t] += u;
        __syncthreads();
    }
    if (t < NB_SCAN) g_bsums[t] = sm[t] - v;
    if (t == 127) g_rowptr[NN] = sm[127];
}
__global__ void k_scan3() {
    int i = blockIdx.x * 1024 + threadIdx.x;
    if (i < NN) {
        int v = g_rowptr[i] + g_bsums[blockIdx.x];
        g_rowptr[i] = v;
        g_cursor[i] = v;
    }
}
__global__ void k_fill(const int* __restrict__ src, const int* __restrict__ dst) {
    int e = blockIdx.x * blockDim.x + threadIdx.x;
    if (e < EE) {
        int d = dst[e];
        int p = atomicAdd(&g_cursor[d], 1);
        g_col[p] = src[e];
    }
}

// ---------------- aggregation (R6 shfl form) ----------------
__global__ void k_gather0(const float* __restrict__ x) {
    int w = (blockIdx.x * blockDim.x + threadIdx.x) >> 5;
    int lane = threadIdx.x & 31;
    if (w >= NN) return;
    float acc = (lane < FF) ? x[(size_t)w * FF + lane] : 0.f;
    int e0 = g_rowptr[w], e1 = g_rowptr[w + 1];
    for (int eb = e0; eb < e1; eb += 32) {
        int n = min(32, e1 - eb);
        int col = (eb + lane < e1) ? g_col[eb + lane] : 0;
        for (int j = 0; j < n; j++) {
            int s = __shfl_sync(0xffffffff, col, j);
            if (lane < FF) acc += x[(size_t)s * FF + lane];
        }
    }
    if (lane < 12) g_z0[(size_t)w * 12 + lane] = (lane < FF) ? acc : 0.f;
}
// fused: h = relu(zb*sc+sh) self + neighbors; z = sum -> bf16 hi/lo arrays (MLP-ready)
__global__ void k_gatherBN() {
    int w = (blockIdx.x * blockDim.x + threadIdx.x) >> 5;
    int lane = threadIdx.x & 31;
    if (w >= NN) return;
    float4 sc = *(const float4*)&g_bnscale[lane << 2];
    float4 sh = *(const float4*)&g_bnshift[lane << 2];
    const float4* hv = (const float4*)g_zb;
    float4 z = hv[(size_t)w * 32 + lane];
    float4 acc;
    acc.x = fmaxf(fmaf(z.x, sc.x, sh.x), 0.f);
    acc.y = fmaxf(fmaf(z.y, sc.y, sh.y), 0.f);
    acc.z = fmaxf(fmaf(z.z, sc.z, sh.z), 0.f);
    acc.w = fmaxf(fmaf(z.w, sc.w, sh.w), 0.f);
    int e0 = g_rowptr[w], e1 = g_rowptr[w + 1];
    for (int eb = e0; eb < e1; eb += 32) {
        int n = min(32, e1 - eb);
        int col = (eb + lane < e1) ? g_col[eb + lane] : 0;
        for (int j = 0; j < n; j++) {
            int s = __shfl_sync(0xffffffff, col, j);
            float4 v = hv[(size_t)s * 32 + lane];
            acc.x += fmaxf(fmaf(v.x, sc.x, sh.x), 0.f);
            acc.y += fmaxf(fmaf(v.y, sc.y, sh.y), 0.f);
            acc.z += fmaxf(fmaf(v.z, sc.z, sh.z), 0.f);
            acc.w += fmaxf(fmaf(v.w, sc.w, sh.w), 0.f);
        }
    }
    float r0, r1, r2, r3;
    uint32_t h01 = pack_hi(acc.x, acc.y, r0, r1);
    uint32_t h23 = pack_hi(acc.z, acc.w, r2, r3);
    ((uint2*)g_zahi)[(size_t)w * 32 + lane] = make_uint2(h01, h23);
    ((uint2*)g_zalo)[(size_t)w * 32 + lane] = make_uint2(pack_lo(r0, r1), pack_lo(r2, r3));
}

// ---------------- persistent tensor-core fused MLP + BN partials ----------------
// grid = 148; weights + biases staged ONCE per block; loop over row tiles staging only A.
template <int K1>
__global__ void __launch_bounds__(256, 1) k_mlp_mma(
    int layer, const float* __restrict__ b1g, const float* __restrict__ b2g)
{
    extern __shared__ char smem[];
    uint32_t sb = smem_u32(smem);
    float* b1s = (float*)(smem + SM_B1);
    float* b2s = (float*)(smem + SM_B2);
    const int t = threadIdx.x, lane = t & 31, wid = t >> 5;
    const int warp_m = wid & 1, warp_n = wid >> 1;

    if (t < 128) { b1s[t] = b1g[t]; b2s[t] = b2g[t]; }

    // ---- stage W1/W2 once ----
    {
        const __nv_bfloat16* w1h = g_w1hi + (size_t)layer * 16384;
        const __nv_bfloat16* w1l = g_w1lo + (size_t)layer * 16384;
        constexpr int KC = K1 / 8;
        for (int i = t; i < 128 * KC; i += 256) {
            int n = i / KC, kk = (i % KC) << 3;
            *(uint4*)(smem + SM_W1HI + (n * TSTR + kk) * 2) = *(const uint4*)(w1h + n * 128 + kk);
            *(uint4*)(smem + SM_W1LO + (n * TSTR + kk) * 2) = *(const uint4*)(w1l + n * 128 + kk);
        }
        const __nv_bfloat16* w2h = g_w2hi + (size_t)layer * 16384;
        const __nv_bfloat16* w2l = g_w2lo + (size_t)layer * 16384;
        for (int i = t; i < 128 * 16; i += 256) {
            int n = i >> 4, kk = (i & 15) << 3;
            *(uint4*)(smem + SM_W2HI + (n * TSTR + kk) * 2) = *(const uint4*)(w2h + n * 128 + kk);
            *(uint4*)(smem + SM_W2LO + (n * TSTR + kk) * 2) = *(const uint4*)(w2l + n * 128 + kk);
        }
    }

    for (int tile = blockIdx.x; tile < NBLK; tile += gridDim.x) {
        const int row0 = tile * 128;
        __syncthreads();   // prior iteration's red_s/red_q reads (aliasing A) complete; W staged (1st iter)

        // ---- stage A tile ----
        if (K1 == 128) {
            const uint4 zero4 = make_uint4(0u, 0u, 0u, 0u);
            for (int i = t; i < 128 * 16; i += 256) {
                int r = i >> 4, kk = (i & 15) << 3;
                int gr = row0 + r;
                uint4 vh = zero4, vl = zero4;
                if (gr < NN) {
                    vh = *(const uint4*)(g_zahi + (size_t)gr * 128 + kk);
                    vl = *(const uint4*)(g_zalo + (size_t)gr * 128 + kk);
                }
                *(uint4*)(smem + SM_AHI + (r * TSTR + kk) * 2) = vh;
                *(uint4*)(smem + SM_ALO + (r * TSTR + kk) * 2) = vl;
            }
        } else {
            for (int i = t; i < 128 * 8; i += 256) {
                int r = i >> 3, c = (i & 7) << 1, gr = row0 + r;
                float a = 0.f, b = 0.f;
                if (gr < NN && c < 9) a = g_z0[(size_t)gr * 12 + c];
                if (gr < NN && c + 1 < 9) b = g_z0[(size_t)gr * 12 + c + 1];
                float ra, rb;
                *(uint32_t*)(smem + SM_AHI + (r * TSTR + c) * 2) = pack_hi(a, b, ra, rb);
                *(uint32_t*)(smem + SM_ALO + (r * TSTR + c) * 2) = pack_lo(ra, rb);
            }
        }
        __syncthreads();

        // ---- GEMM1 ----
        float acc[4][4][4];
#pragma unroll
        for (int mt = 0; mt < 4; mt++)
#pragma unroll
            for (int nt = 0; nt < 4; nt++)
#pragma unroll
                for (int i = 0; i < 4; i++) acc[mt][nt][i] = 0.f;
        gemm3<K1 / 16>(sb + SM_AHI, sb + SM_ALO, sb + SM_W1HI, sb + SM_W1LO, warp_m, warp_n, lane, acc);
        __syncthreads();

        // ---- epilogue1: Y = relu(D1 + b1) -> A hi/lo ----
#pragma unroll
        for (int mt = 0; mt < 4; mt++) {
#pragma unroll
            for (int nt = 0; nt < 4; nt++) {
                int r1 = warp_m * 64 + mt * 16 + (lane >> 2);
                int r2 = r1 + 8;
                int c = warp_n * 32 + nt * 8 + ((lane & 3) << 1);
                float bb0 = b1s[c], bb1 = b1s[c + 1];
                float y00 = fmaxf(acc[mt][nt][0] + bb0, 0.f);
                float y01 = fmaxf(acc[mt][nt][1] + bb1, 0.f);
                float y10 = fmaxf(acc[mt][nt][2] + bb0, 0.f);
                float y11 = fmaxf(acc[mt][nt][3] + bb1, 0.f);
                float ra, rb;
                *(uint32_t*)(smem + SM_AHI + (r1 * TSTR + c) * 2) = pack_hi(y00, y01, ra, rb);
                *(uint32_t*)(smem + SM_ALO + (r1 * TSTR + c) * 2) = pack_lo(ra, rb);
                *(uint32_t*)(smem + SM_AHI + (r2 * TSTR + c) * 2) = pack_hi(y10, y11, ra, rb);
                *(uint32_t*)(smem + SM_ALO + (r2 * TSTR + c) * 2) = pack_lo(ra, rb);
            }
        }
        __syncthreads();

        // ---- GEMM2 ----
#pragma unroll
        for (int mt = 0; mt < 4; mt++)
#pragma unroll
            for (int nt = 0; nt < 4; nt++)
#pragma unroll
                for (int i = 0; i < 4; i++) acc[mt][nt][i] = 0.f;
        gemm3<8>(sb + SM_AHI, sb + SM_ALO, sb + SM_W2HI, sb + SM_W2LO, warp_m, warp_n, lane, acc);
        __syncthreads();

        // ---- epilogue2: y = D2 + b2 -> g_zb ; BN partials ----
        float s[8], q[8];
#pragma unroll
        for (int i = 0; i < 8; i++) { s[i] = 0.f; q[i] = 0.f; }
#pragma unroll
        for (int mt = 0; mt < 4; mt++) {
#pragma unroll
            for (int nt = 0; nt < 4; nt++) {
                int r1 = warp_m * 64 + mt * 16 + (lane >> 2);
                int r2 = r1 + 8;
                int c = warp_n * 32 + nt * 8 + ((lane & 3) << 1);
                int gr1 = row0 + r1, gr2 = row0 + r2;
                float bb0 = b2s[c], bb1 = b2s[c + 1];
                float y00 = acc[mt][nt][0] + bb0, y01 = acc[mt][nt][1] + bb1;
                float y10 = acc[mt][nt][2] + bb0, y11 = acc[mt][nt][3] + bb1;
                if (gr1 < NN) {
                    *(float2*)(g_zb + (size_t)gr1 * 128 + c) = make_float2(y00, y01);
                    s[nt * 2] += y00; q[nt * 2] += y00 * y00;
                    s[nt * 2 + 1] += y01; q[nt * 2 + 1] += y01 * y01;
                }
                if (gr2 < NN) {
                    *(float2*)(g_zb + (size_t)gr2 * 128 + c) = make_float2(y10, y11);
                    s[nt * 2] += y10; q[nt * 2] += y10 * y10;
                    s[nt * 2 + 1] += y11; q[nt * 2 + 1] += y11 * y11;
                }
            }
        }
        float* red_s = (float*)(smem + SM_REDS);
        float* red_q = (float*)(smem + SM_REDQ);
        int slot = warp_m * 8 + (lane >> 2);
#pragma unroll
        for (int nt = 0; nt < 4; nt++) {
#pragma unroll
            for (int p = 0; p < 2; p++) {
                int col = warp_n * 32 + nt * 8 + ((lane & 3) << 1) + p;
                red_s[slot * 128 + col] = s[nt * 2 + p];
                red_q[slot * 128 + col] = q[nt * 2 + p];
            }
        }
        __syncthreads();
        if (t < 128) {
            float S = 0.f, Q = 0.f;
#pragma unroll
            for (int sl = 0; sl < 16; sl++) { S += red_s[sl * 128 + t]; Q += red_q[sl * 128 + t]; }
            g_partsum[tile * 128 + t] = S;
            g_partsq[tile * 128 + t] = Q;
        }
    }
}

// ---------------- BN stats + final normalize ----------------
__global__ void k_bnstats(const float* __restrict__ gamma, const float* __restrict__ beta) {
    __shared__ float ssum[1024], ssq[1024];
    int c = threadIdx.x & 127;
    int p = threadIdx.x >> 7;
    float S = 0.f, Q = 0.f;
    for (int b = p; b < NBLK; b += 8) {
        S += g_partsum[b * 128 + c];
        Q += g_partsq[b * 128 + c];
    }
    ssum[threadIdx.x] = S;
    ssq[threadIdx.x] = Q;
    __syncthreads();
    if (p == 0) {
        for (int r = 1; r < 8; r++) { S += ssum[r * 128 + c]; Q += ssq[r * 128 + c]; }
        float mean = S * (1.0f / NN);
        float var = Q * (1.0f / NN) - mean * mean;
        float e = var + 1e-5f;
        float inv = rsqrtf(e);
        inv = inv * (1.5f - 0.5f * e * inv * inv);
        float sc = inv * gamma[c];
        g_bnscale[c] = sc;
        g_bnshift[c] = beta[c] - mean * sc;
    }
}
__global__ void k_bnnorm(float* __restrict__ out) {
    int i = blockIdx.x * 256 + threadIdx.x;
    if (i >= NN * 32) return;
    int c4 = (i & 31) << 2;
    float4 v = ((const float4*)g_zb)[i];
    float4 sc = *(const float4*)&g_bnscale[c4];
    float4 sh = *(const float4*)&g_bnshift[c4];
    v.x = fmaxf(fmaf(v.x, sc.x, sh.x), 0.f);
    v.y = fmaxf(fmaf(v.y, sc.y, sh.y), 0.f);
    v.z = fmaxf(fmaf(v.z, sc.z, sh.z), 0.f);
    v.w = fmaxf(fmaf(v.w, sc.w, sh.w), 0.f);
    ((float4*)out)[i] = v;
}
__global__ void k_copybatch(const int* __restrict__ b, float* __restrict__ o) {
    int i = blockIdx.x * 256 + threadIdx.x;
    if (i < NN) o[i] = (float)b[i];
}

// ---------------- launch ----------------
extern "C" void kernel_launch(void* const* d_in, const int* in_sizes, int n_in,
                              void* d_out, int out_size) {
    const float* x       = (const float*)d_in[0];
    const int*   ei      = (const int*)d_in[1];
    const int*   batch   = (const int*)d_in[2];
    const float* w1_0    = (const float*)d_in[3];
    const float* b1_0    = (const float*)d_in[4];
    const float* w2_0    = (const float*)d_in[5];
    const float* b2_0    = (const float*)d_in[6];
    const float* gamma_0 = (const float*)d_in[7];
    const float* beta_0  = (const float*)d_in[8];
    const float* ws1     = (const float*)d_in[9];
    const float* bs1     = (const float*)d_in[10];
    const float* ws2     = (const float*)d_in[11];
    const float* bs2     = (const float*)d_in[12];
    const float* gammas  = (const float*)d_in[13];
    const float* betas   = (const float*)d_in[14];
    float* out = (float*)d_out;

    cudaFuncSetAttribute(k_mlp_mma<16>,  cudaFuncAttributeMaxDynamicSharedMemorySize, SM_TOTAL);
    cudaFuncSetAttribute(k_mlp_mma<128>, cudaFuncAttributeMaxDynamicSharedMemorySize, SM_TOTAL);

    void* curp = nullptr;
    cudaGetSymbolAddress(&curp, g_cursor);

    const int* src = ei;
    const int* dst = ei + EE;

    // ---- weight pre-conversion + CSR build ----
    k_wconv<<<(5 * 16384 * 2 + 255) / 256, 256>>>(w1_0, w2_0, ws1, ws2);
    cudaMemsetAsync(curp, 0, NN * sizeof(int), 0);
    k_hist<<<(EE + 511) / 512, 512>>>(dst);
    k_scan1<<<NB_SCAN, 1024>>>();
    k_scan2<<<1, 128>>>();
    k_scan3<<<NB_SCAN, 1024>>>();
    k_fill<<<(EE + 511) / 512, 512>>>(src, dst);

    const int GBLK = (NN * 32 + 255) / 256;

    // ---- layer 0 (F=9 -> H) ----
    k_gather0<<<GBLK, 256>>>(x);
    k_mlp_mma<16><<<148, 256, SM_TOTAL>>>(0, b1_0, b2_0);
    k_bnstats<<<1, 1024>>>(gamma_0, beta_0);

    // ---- layers 1..4 ----
    for (int l = 0; l < 4; l++) {
        const float* b1 = bs1 + (size_t)l * HH;
        const float* b2 = bs2 + (size_t)l * HH;
        const float* ga = gammas + (size_t)l * HH;
        const float* be = betas + (size_t)l * HH;
        k_gatherBN<<<GBLK, 256>>>();
        k_mlp_mma<128><<<148, 256, SM_TOTAL>>>(l + 1, b1, b2);
        k_bnstats<<<1, 1024>>>(ga, be);
    }
    // final normalize -> out
    k_bnnorm<<<(NN * 32 + 255) / 256, 256>>>(out);

    // ---- batch passthrough (float-converted) ----
    {
        float* bo = out + ((size_t)NN * HH);
        k_copybatch<<<(NN + 255) / 256, 256>>>(batch, bo);
    }
}